// round 12
// baseline (speedup 1.0000x reference)
#include <cuda_runtime.h>
#include <cuda_fp16.h>
#include <cstddef>

// GCNConv(16,8): out = D^-1/2 (A+I) D^-1/2 X W^T + b
// fp16 message payload: hs stored as half, accumulated with ONE
// red.global.add.noftz.v4.f16x2 per edge (8 channels / 128 bits).
//   hs[n]   = dinv[n] * (x[n] @ W^T)        (fp32 math, fp16 store)
//   acc[n]  = hs[n] + sum hs[src]           (fp16 RED into g_acc)
//   out[n]  = float(acc[n])*dinv[n] + b     (fp32 epilogue)

#define MAXN 500000

__device__ __half g_hs [(size_t)MAXN * 8];   // 8 MB, L2-resident
__device__ __half g_acc[(size_t)MAXN * 8];   // 8 MB accumulator
__device__ float  g_dinv[MAXN];
__device__ int    g_deg[MAXN];

// ---------------------------------------------------------------- degree count (4 edges/thread, R7)
__global__ void k_deg(const int* __restrict__ dst, int E, int N) {
    int i = blockIdx.x * blockDim.x + threadIdx.x;
    int e = i * 4;
    if (e + 3 < E) {
        int4 d4 = __ldcs((const int4*)(dst + e));
        if ((unsigned)d4.x < (unsigned)N) atomicAdd(&g_deg[d4.x], 1);
        if ((unsigned)d4.y < (unsigned)N) atomicAdd(&g_deg[d4.y], 1);
        if ((unsigned)d4.z < (unsigned)N) atomicAdd(&g_deg[d4.z], 1);
        if ((unsigned)d4.w < (unsigned)N) atomicAdd(&g_deg[d4.w], 1);
    } else {
        for (; e < E; e++) {
            int d = dst[e];
            if ((unsigned)d < (unsigned)N) atomicAdd(&g_deg[d], 1);
        }
    }
}

// ---------------------------------------------------------------- node transform
// hs = dinv * (x @ W^T) in fp32; stored fp16 to g_hs and g_acc (self-loop init).
__global__ void k_node(const float* __restrict__ x, const float* __restrict__ W, int N) {
    __shared__ float sW[128];               // W is [8,16] row-major
    int t = threadIdx.x;
    if (t < 128) sW[t] = W[t];
    __syncthreads();

    int n = blockIdx.x * blockDim.x + t;
    if (n >= N) return;

    const float4* xp = (const float4*)(x + (size_t)n * 16);
    float4 v0 = __ldcs(xp), v1 = __ldcs(xp + 1), v2 = __ldcs(xp + 2), v3 = __ldcs(xp + 3);
    float xr[16] = { v0.x, v0.y, v0.z, v0.w,  v1.x, v1.y, v1.z, v1.w,
                     v2.x, v2.y, v2.z, v2.w,  v3.x, v3.y, v3.z, v3.w };

    float dinv = rsqrtf((float)(g_deg[n] + 1));   // +1 self loop; always > 0
    g_dinv[n] = dinv;

    float h[8];
#pragma unroll
    for (int j = 0; j < 8; j++) {
        float s = 0.f;
#pragma unroll
        for (int i = 0; i < 16; i++) s = fmaf(xr[i], sW[j * 16 + i], s);
        h[j] = s * dinv;
    }

    __half2 q0 = __floats2half2_rn(h[0], h[1]);
    __half2 q1 = __floats2half2_rn(h[2], h[3]);
    __half2 q2 = __floats2half2_rn(h[4], h[5]);
    __half2 q3 = __floats2half2_rn(h[6], h[7]);
    uint4 pk = make_uint4(*(unsigned*)&q0, *(unsigned*)&q1,
                          *(unsigned*)&q2, *(unsigned*)&q3);

    *(uint4*)(g_hs  + (size_t)n * 8) = pk;
    *(uint4*)(g_acc + (size_t)n * 8) = pk;  // accumulator init = self-loop msg
}

// ---------------------------------------------------------------- edge scatter
// acc[dst] += hs[src], 2 edges/thread, ONE v4.f16x2 RED per edge.
__global__ void k_scatter(const int* __restrict__ src,
                          const int* __restrict__ dst, int E, int N) {
    int i = blockIdx.x * blockDim.x + threadIdx.x;
    int e = i * 2;
    if (e >= E) return;

    int2 s2, d2;
    if (e + 1 < E) {
        s2 = __ldcs((const int2*)(src + e));
        d2 = __ldcs((const int2*)(dst + e));
    } else {
        s2.x = src[e]; d2.x = dst[e];
        s2.y = 0;      d2.y = -1;           // fails bounds check
    }

#pragma unroll
    for (int j = 0; j < 2; j++) {
        int s = j ? s2.y : s2.x;
        int d = j ? d2.y : d2.x;
        if ((unsigned)s >= (unsigned)N || (unsigned)d >= (unsigned)N) continue;

        uint4 m = *(const uint4*)(g_hs + (size_t)s * 8);   // 16B row, fp16x8
        __half* dp = g_acc + (size_t)d * 8;                // 16B-aligned
        asm volatile("red.global.add.noftz.v4.f16x2 [%0], {%1,%2,%3,%4};"
                     :: "l"(dp), "r"(m.x), "r"(m.y), "r"(m.z), "r"(m.w)
                     : "memory");
    }
}

// ---------------------------------------------------------------- finalize: out = float(acc)*dinv + b
__global__ void k_final(const float* __restrict__ bias, float* __restrict__ out, int N) {
    int n = blockIdx.x * blockDim.x + threadIdx.x;
    if (n >= N) return;

    float dinv = g_dinv[n];
    const float4* bp = (const float4*)bias;
    float4 b0 = __ldg(bp), b1 = __ldg(bp + 1);

    uint4 r = *(const uint4*)(g_acc + (size_t)n * 8);
    float2 f0 = __half22float2(*(__half2*)&r.x);
    float2 f1 = __half22float2(*(__half2*)&r.y);
    float2 f2 = __half22float2(*(__half2*)&r.z);
    float2 f3 = __half22float2(*(__half2*)&r.w);

    float4 o0 = make_float4(fmaf(f0.x, dinv, b0.x), fmaf(f0.y, dinv, b0.y),
                            fmaf(f1.x, dinv, b0.z), fmaf(f1.y, dinv, b0.w));
    float4 o1 = make_float4(fmaf(f2.x, dinv, b1.x), fmaf(f2.y, dinv, b1.y),
                            fmaf(f3.x, dinv, b1.z), fmaf(f3.y, dinv, b1.w));

    float4* op = (float4*)(out + (size_t)n * 8);
    op[0] = o0;
    op[1] = o1;
}

// ---------------------------------------------------------------- launch
extern "C" void kernel_launch(void* const* d_in, const int* in_sizes, int n_in,
                              void* d_out, int out_size) {
    const float* x    = (const float*)d_in[0];   // [N,16] f32
    const int*   ei   = (const int*)d_in[1];     // [2,E]  int32 (converted from int64)
    const float* W    = (const float*)d_in[2];   // [8,16] f32
    const float* bias = (const float*)d_in[3];   // [8]    f32
    float*       out  = (float*)d_out;           // [N,8]  f32

    int N = in_sizes[0] / 16;
    int E = in_sizes[1] / 2;
    const int* src = ei;
    const int* dst = ei + E;

    const int T = 256;
    int gbN  = (N + T - 1) / T;
    int gbE4 = (E / 4 + T - 1) / T + 1;      // 4 edges/thread (+1 tail block)
    int gbE2 = ((E + 1) / 2 + T - 1) / T;    // 2 edges/thread

    void* degp = nullptr;
    cudaGetSymbolAddress(&degp, g_deg);      // address query only, no allocation
    cudaMemsetAsync(degp, 0, (size_t)N * sizeof(int));

    k_deg<<<gbE4, T>>>(dst, E, N);
    k_node<<<gbN, T>>>(x, W, N);
    k_scatter<<<gbE2, T>>>(src, dst, E, N);
    k_final<<<gbN, T>>>(bias, out, N);
}